// round 1
// baseline (speedup 1.0000x reference)
#include <cuda_runtime.h>

// Problem constants
#define B_   16
#define L_   1024
#define D_   512
#define H_   8
#define DK_  64
#define M_ROWS   (B_ * L_)            // 16384
#define TOK_ELEMS  (B_ * L_ * D_)     // 8388608
#define PROJ_ELEMS (B_ * H_ * L_ * DK_) // 8388608

// Output layout: [out (B,LQ,D) | attn_out (B,LQ,H,LK)]
#define OUT0_ELEMS ((size_t)B_ * L_ * D_)

// ---------------- scratch (device globals; no allocation allowed) -------------
__device__ float g_sat_ln[TOK_ELEMS];
__device__ float g_ts_ln[TOK_ELEMS];
__device__ float g_q[PROJ_ELEMS];
__device__ float g_k[PROJ_ELEMS];
__device__ float g_ss[PROJ_ELEMS];   // sin_sat
__device__ float g_cs[PROJ_ELEMS];   // cos_sat
__device__ float g_st[PROJ_ELEMS];   // sin_ts
__device__ float g_ct[PROJ_ELEMS];   // cos_ts
__device__ float g_v[B_ * L_ * DK_];
__device__ float g_head[PROJ_ELEMS];

// ---------------- LayerNorm ---------------------------------------------------
// grid: 2*M_ROWS blocks, 128 threads; each thread handles one float4 of a 512 row
__global__ void ln_kernel(const float* __restrict__ sat, const float* __restrict__ ts,
                          const float* __restrict__ gs, const float* __restrict__ bs,
                          const float* __restrict__ gt, const float* __restrict__ bt)
{
    int rid = blockIdx.x;
    const float* src; float* dst; const float* g; const float* bb;
    if (rid < M_ROWS) {
        src = sat + (size_t)rid * D_; dst = g_sat_ln + (size_t)rid * D_; g = gs; bb = bs;
    } else {
        int r = rid - M_ROWS;
        src = ts + (size_t)r * D_;   dst = g_ts_ln + (size_t)r * D_;  g = gt; bb = bt;
    }
    int t = threadIdx.x;
    float4 x = ((const float4*)src)[t];
    float s  = x.x + x.y + x.z + x.w;
    float sq = x.x*x.x + x.y*x.y + x.z*x.z + x.w*x.w;
    #pragma unroll
    for (int o = 16; o; o >>= 1) {
        s  += __shfl_xor_sync(0xFFFFFFFFu, s,  o);
        sq += __shfl_xor_sync(0xFFFFFFFFu, sq, o);
    }
    __shared__ float ws[4], wq[4];
    if ((t & 31) == 0) { ws[t >> 5] = s; wq[t >> 5] = sq; }
    __syncthreads();
    s  = ws[0] + ws[1] + ws[2] + ws[3];
    sq = wq[0] + wq[1] + wq[2] + wq[3];
    float m   = s * (1.0f / D_);
    float var = sq * (1.0f / D_) - m * m;
    float inv = rsqrtf(var + 1e-5f);
    float4 g4 = ((const float4*)g)[t];
    float4 b4 = ((const float4*)bb)[t];
    float4 o;
    o.x = (x.x - m) * inv * g4.x + b4.x;
    o.y = (x.y - m) * inv * g4.y + b4.y;
    o.z = (x.z - m) * inv * g4.z + b4.z;
    o.w = (x.w - m) * inv * g4.w + b4.w;
    ((float4*)dst)[t] = o;
}

// ---------------- projection GEMM ---------------------------------------------
// C[(b, h, l, :64)] = A[(b l), :512] @ W[h, :512, :64] + bias[h, :64]
// A: (16384, 512) row-major.  W: (Hn, 512, 64).  grid: (Hn, 16384/128), block 256.
__global__ void __launch_bounds__(256) proj_gemm(const float* __restrict__ A,
                                                 const float* __restrict__ W,
                                                 const float* __restrict__ bias,
                                                 float* __restrict__ C, int Hn)
{
    __shared__ __align__(16) float Ast[16][128];   // transposed A tile
    __shared__ __align__(16) float Ws[16][64];
    int h  = blockIdx.x;
    int m0 = blockIdx.y * 128;
    int tid = threadIdx.x;
    int ty = tid >> 4, tx = tid & 15;   // 16x16 thread grid, tile 8x4 per thread
    const float* Wp = W + (size_t)h * (D_ * 64);

    float acc[8][4];
    #pragma unroll
    for (int i = 0; i < 8; i++)
        #pragma unroll
        for (int j = 0; j < 4; j++) acc[i][j] = 0.0f;

    for (int k0 = 0; k0 < D_; k0 += 16) {
        // A tile: 128x16 = 512 float4 loads, stored transposed
        #pragma unroll
        for (int i = 0; i < 2; i++) {
            int e = tid + i * 256;
            int r = e >> 2, c4 = e & 3;
            float4 a = *(const float4*)&A[(size_t)(m0 + r) * D_ + k0 + c4 * 4];
            Ast[c4 * 4 + 0][r] = a.x;
            Ast[c4 * 4 + 1][r] = a.y;
            Ast[c4 * 4 + 2][r] = a.z;
            Ast[c4 * 4 + 3][r] = a.w;
        }
        {   // W tile: 16x64 = 256 float4
            int r = tid >> 4, c4 = tid & 15;
            *(float4*)&Ws[r][c4 * 4] = *(const float4*)&Wp[(size_t)(k0 + r) * 64 + c4 * 4];
        }
        __syncthreads();
        #pragma unroll
        for (int kk = 0; kk < 16; kk++) {
            float4 a0 = *(float4*)&Ast[kk][ty * 8];
            float4 a1 = *(float4*)&Ast[kk][ty * 8 + 4];
            float4 b0 = *(float4*)&Ws[kk][tx * 4];
            float av[8] = {a0.x, a0.y, a0.z, a0.w, a1.x, a1.y, a1.z, a1.w};
            float bv[4] = {b0.x, b0.y, b0.z, b0.w};
            #pragma unroll
            for (int i = 0; i < 8; i++)
                #pragma unroll
                for (int j = 0; j < 4; j++)
                    acc[i][j] += av[i] * bv[j];
        }
        __syncthreads();
    }
    float4 bia = *(const float4*)&bias[h * 64 + tx * 4];
    #pragma unroll
    for (int i = 0; i < 8; i++) {
        int m = m0 + ty * 8 + i;
        int bb = m >> 10, l = m & 1023;
        float4 o;
        o.x = acc[i][0] + bia.x;
        o.y = acc[i][1] + bia.y;
        o.z = acc[i][2] + bia.z;
        o.w = acc[i][3] + bia.w;
        *(float4*)&C[(((size_t)(bb * Hn + h) << 10) + l) * 64 + tx * 4] = o;
    }
}

// ---------------- RoPE (in place on q and k) ----------------------------------
// out[2j]   = x[2j]*cos[2j]   - x[2j+1]*sin[2j]
// out[2j+1] = x[2j+1]*cos[2j+1] + x[2j]*sin[2j+1]
__global__ void rope_kernel()
{
    const int Np = PROJ_ELEMS / 2;   // pairs per tensor
    int idx = blockIdx.x * blockDim.x + threadIdx.x;
    float2 *xb; const float2 *cb, *sb;
    if (idx < Np) {
        xb = (float2*)g_q; cb = (const float2*)g_ct; sb = (const float2*)g_st;
    } else {
        idx -= Np;
        xb = (float2*)g_k; cb = (const float2*)g_cs; sb = (const float2*)g_ss;
    }
    float2 x = xb[idx];
    float2 c = cb[idx];
    float2 s = sb[idx];
    float2 o;
    o.x = x.x * c.x - x.y * s.x;
    o.y = x.y * c.y + x.x * s.y;
    xb[idx] = o;
}

// ---------------- attention ---------------------------------------------------
#define QT  32
#define KT  256
#define SCP 1025     // padded score row stride
#define KVP 68       // padded k/v tile row stride
#define ATTN_SMEM_FLOATS (QT * SCP + KT * KVP + QT * 64)

__global__ void __launch_bounds__(256) attn_kernel(float* __restrict__ attn_out)
{
    extern __shared__ __align__(16) float sm[];
    float* sc = sm;                  // QT x SCP
    float* kv = sm + QT * SCP;       // KT x KVP
    float* qs = kv + KT * KVP;       // QT x 64

    int tid = threadIdx.x;
    int q0 = blockIdx.x * QT;
    int h  = blockIdx.y;
    int b  = blockIdx.z;
    size_t bh = (size_t)(b * H_ + h);

    // load q tile (32x64)
    size_t qbase = ((bh << 10) + q0) * 64;
    #pragma unroll
    for (int i = 0; i < 2; i++) {
        int e = tid + i * 256;
        ((float4*)qs)[e] = *(const float4*)&g_q[qbase + (size_t)e * 4];
    }

    int ty = tid >> 5, tx = tid & 31;

    // ---- scores ----
    for (int kt = 0; kt < 4; kt++) {
        __syncthreads();  // kv free to overwrite; also orders qs load at kt=0
        size_t kbase = ((bh << 10) + kt * KT) * 64;
        #pragma unroll
        for (int i = 0; i < 16; i++) {
            int e = tid + i * 256;          // 4096 float4s
            int r = e >> 4, c4 = e & 15;
            float4 a = *(const float4*)&g_k[kbase + (size_t)r * 64 + c4 * 4];
            *(float4*)&kv[r * KVP + c4 * 4] = a;
        }
        __syncthreads();
        float acc[4][8];
        #pragma unroll
        for (int i = 0; i < 4; i++)
            #pragma unroll
            for (int j = 0; j < 8; j++) acc[i][j] = 0.0f;
        #pragma unroll
        for (int d = 0; d < 64; d += 4) {
            float4 a[4];
            #pragma unroll
            for (int i = 0; i < 4; i++) a[i] = *(float4*)&qs[(ty * 4 + i) * 64 + d];
            #pragma unroll
            for (int j = 0; j < 8; j++) {
                float4 bk = *(float4*)&kv[(tx + 32 * j) * KVP + d];
                #pragma unroll
                for (int i = 0; i < 4; i++)
                    acc[i][j] += a[i].x * bk.x + a[i].y * bk.y + a[i].z * bk.z + a[i].w * bk.w;
            }
        }
        #pragma unroll
        for (int i = 0; i < 4; i++)
            #pragma unroll
            for (int j = 0; j < 8; j++)
                sc[(ty * 4 + i) * SCP + kt * KT + tx + 32 * j] = acc[i][j] * 0.125f;
    }
    __syncthreads();

    // ---- softmax (warp ty owns rows ty*4 .. ty*4+3; lane tx strides by 32) ----
    for (int rr = ty * 4; rr < ty * 4 + 4; rr++) {
        float vals[32];
        float mx = -1e30f;
        #pragma unroll
        for (int j = 0; j < 32; j++) {
            vals[j] = sc[rr * SCP + tx + 32 * j];
            mx = fmaxf(mx, vals[j]);
        }
        #pragma unroll
        for (int o = 16; o; o >>= 1) mx = fmaxf(mx, __shfl_xor_sync(0xFFFFFFFFu, mx, o));
        float s = 0.0f;
        #pragma unroll
        for (int j = 0; j < 32; j++) { vals[j] = __expf(vals[j] - mx); s += vals[j]; }
        #pragma unroll
        for (int o = 16; o; o >>= 1) s += __shfl_xor_sync(0xFFFFFFFFu, s, o);
        float inv = 1.0f / s;
        size_t obase = (((size_t)(b * L_ + q0 + rr) * H_ + h) << 10);
        #pragma unroll
        for (int j = 0; j < 32; j++) {
            float p = vals[j] * inv;
            sc[rr * SCP + tx + 32 * j] = p;
            attn_out[obase + tx + 32 * j] = p;
        }
    }
    __syncthreads();

    // ---- head = P @ V  (32x64) ----
    int r0 = (tid & 7) * 4;
    int c0 = (tid >> 3) * 2;
    float hacc[4][2];
    #pragma unroll
    for (int i = 0; i < 4; i++) { hacc[i][0] = 0.0f; hacc[i][1] = 0.0f; }
    for (int vt = 0; vt < 4; vt++) {
        __syncthreads();
        size_t vbase = ((size_t)b * L_ + vt * KT) * 64;
        #pragma unroll
        for (int i = 0; i < 16; i++) {
            int e = tid + i * 256;
            int r = e >> 4, c4 = e & 15;
            float4 a = *(const float4*)&g_v[vbase + (size_t)r * 64 + c4 * 4];
            *(float4*)&kv[r * KVP + c4 * 4] = a;
        }
        __syncthreads();
        #pragma unroll 4
        for (int kk = 0; kk < KT; kk++) {
            float v0 = kv[kk * KVP + c0];
            float v1 = kv[kk * KVP + c0 + 1];
            #pragma unroll
            for (int i = 0; i < 4; i++) {
                float p = sc[(r0 + i) * SCP + vt * KT + kk];
                hacc[i][0] += p * v0;
                hacc[i][1] += p * v1;
            }
        }
    }
    #pragma unroll
    for (int i = 0; i < 4; i++) {
        size_t hb = ((bh << 10) + q0 + r0 + i) * 64 + c0;
        g_head[hb]     = hacc[i][0];
        g_head[hb + 1] = hacc[i][1];
    }
}

// ---------------- final: out = mean_h(head) @ Wh ------------------------------
// grid 2048 (8 q-rows each), block 256; Wh (64x512) resident in smem
__global__ void __launch_bounds__(256) out_kernel(const float* __restrict__ Wh,
                                                  float* __restrict__ out)
{
    extern __shared__ __align__(16) float sm2[];   // 64*512 floats
    __shared__ float hm[8][64];
    int tid = threadIdx.x;
    int m0 = blockIdx.x * 8;
    int bb = m0 >> 10;
    int l0 = m0 & 1023;

    #pragma unroll
    for (int i = 0; i < 32; i++) {
        int e = tid + i * 256;
        ((float4*)sm2)[e] = ((const float4*)Wh)[e];
    }
    #pragma unroll
    for (int i = 0; i < 2; i++) {
        int e = tid + i * 256;
        int r = e >> 6, kk = e & 63;
        float s = 0.0f;
        #pragma unroll
        for (int hh = 0; hh < 8; hh++)
            s += g_head[(((size_t)(bb * H_ + hh) << 10) + l0 + r) * 64 + kk];
        hm[r][kk] = s * 0.125f;
    }
    __syncthreads();

    int ty = tid >> 6;       // rows ty*2, ty*2+1
    int tx = tid & 63;       // cols tx*8 .. tx*8+7
    float acc[2][8];
    #pragma unroll
    for (int i = 0; i < 2; i++)
        #pragma unroll
        for (int j = 0; j < 8; j++) acc[i][j] = 0.0f;
    #pragma unroll 8
    for (int d = 0; d < 64; d++) {
        float a0 = hm[ty * 2][d];
        float a1 = hm[ty * 2 + 1][d];
        float4 w0 = *(float4*)&sm2[d * 512 + tx * 8];
        float4 w1 = *(float4*)&sm2[d * 512 + tx * 8 + 4];
        acc[0][0] += a0 * w0.x; acc[0][1] += a0 * w0.y; acc[0][2] += a0 * w0.z; acc[0][3] += a0 * w0.w;
        acc[0][4] += a0 * w1.x; acc[0][5] += a0 * w1.y; acc[0][6] += a0 * w1.z; acc[0][7] += a0 * w1.w;
        acc[1][0] += a1 * w0.x; acc[1][1] += a1 * w0.y; acc[1][2] += a1 * w0.z; acc[1][3] += a1 * w0.w;
        acc[1][4] += a1 * w1.x; acc[1][5] += a1 * w1.y; acc[1][6] += a1 * w1.z; acc[1][7] += a1 * w1.w;
    }
    #pragma unroll
    for (int i = 0; i < 2; i++) {
        int m = m0 + ty * 2 + i;
        float4 o0 = {acc[i][0], acc[i][1], acc[i][2], acc[i][3]};
        float4 o1 = {acc[i][4], acc[i][5], acc[i][6], acc[i][7]};
        *(float4*)&out[(size_t)m * 512 + tx * 8]     = o0;
        *(float4*)&out[(size_t)m * 512 + tx * 8 + 4] = o1;
    }
}

// ---------------- launch ------------------------------------------------------
extern "C" void kernel_launch(void* const* d_in, const int* in_sizes, int n_in,
                              void* d_out, int out_size)
{
    const float* sat     = (const float*)d_in[0];
    const float* satpos  = (const float*)d_in[1];
    const float* ts      = (const float*)d_in[2];
    const float* tspos   = (const float*)d_in[3];
    const float* lsg     = (const float*)d_in[4];
    const float* lsb     = (const float*)d_in[5];
    const float* ltg     = (const float*)d_in[6];
    const float* ltb     = (const float*)d_in[7];
    const float* Wv      = (const float*)d_in[8];
    const float* bv      = (const float*)d_in[9];
    const float* Wq      = (const float*)d_in[10];
    const float* bq      = (const float*)d_in[11];
    const float* Wk      = (const float*)d_in[12];
    const float* bk      = (const float*)d_in[13];
    const float* Wsat    = (const float*)d_in[14];
    const float* bsat    = (const float*)d_in[15];
    const float* Wts     = (const float*)d_in[16];
    const float* bts     = (const float*)d_in[17];
    const float* Wh      = (const float*)d_in[18];

    float* out      = (float*)d_out;
    float* attn_out = out + OUT0_ELEMS;

    // resolve scratch symbol addresses (host API, not a stream op; capture-safe)
    float *p_satln, *p_tsln, *p_q, *p_k, *p_ss, *p_cs, *p_st, *p_ct, *p_v;
    cudaGetSymbolAddress((void**)&p_satln, g_sat_ln);
    cudaGetSymbolAddress((void**)&p_tsln,  g_ts_ln);
    cudaGetSymbolAddress((void**)&p_q,     g_q);
    cudaGetSymbolAddress((void**)&p_k,     g_k);
    cudaGetSymbolAddress((void**)&p_ss,    g_ss);
    cudaGetSymbolAddress((void**)&p_cs,    g_cs);
    cudaGetSymbolAddress((void**)&p_st,    g_st);
    cudaGetSymbolAddress((void**)&p_ct,    g_ct);
    cudaGetSymbolAddress((void**)&p_v,     g_v);

    const int attn_smem = ATTN_SMEM_FLOATS * 4;   // 209024 bytes
    cudaFuncSetAttribute(attn_kernel, cudaFuncAttributeMaxDynamicSharedMemorySize, attn_smem);
    cudaFuncSetAttribute(out_kernel,  cudaFuncAttributeMaxDynamicSharedMemorySize, 64 * 512 * 4);

    // 1. LayerNorms
    ln_kernel<<<2 * M_ROWS, 128>>>(sat, ts, lsg, lsb, ltg, ltb);

    // 2. projections (generic GEMM)
    dim3 g1(1, M_ROWS / 128), g8(H_, M_ROWS / 128);
    proj_gemm<<<g1, 256>>>(p_satln, Wv,   bv,   p_v,  1);
    proj_gemm<<<g8, 256>>>(p_tsln,  Wq,   bq,   p_q,  H_);
    proj_gemm<<<g8, 256>>>(p_satln, Wk,   bk,   p_k,  H_);
    proj_gemm<<<g8, 256>>>(satpos,                Wsat, bsat, p_ss, H_);
    proj_gemm<<<g8, 256>>>(satpos + TOK_ELEMS,    Wsat, bsat, p_cs, H_);
    proj_gemm<<<g8, 256>>>(tspos,                 Wts,  bts,  p_st, H_);
    proj_gemm<<<g8, 256>>>(tspos + TOK_ELEMS,     Wts,  bts,  p_ct, H_);

    // 3. RoPE in place on q and k
    rope_kernel<<<PROJ_ELEMS / 256, 256>>>();

    // 4. attention: scores, softmax, attn_out, P@V
    dim3 ga(L_ / QT, H_, B_);
    attn_kernel<<<ga, 256, attn_smem>>>(attn_out);

    // 5. out = mean_h(head) @ Wh
    out_kernel<<<M_ROWS / 8, 256, 64 * 512 * 4>>>(Wh, out);
}

// round 4
// speedup vs baseline: 1.1505x; 1.1505x over previous
#include <cuda_runtime.h>
#include <cstdint>

// Problem constants
#define B_   16
#define L_   1024
#define D_   512
#define H_   8
#define DK_  64
#define M_ROWS   (B_ * L_)            // 16384
#define TOK_ELEMS  (B_ * L_ * D_)     // 8388608
#define PROJ_ELEMS (B_ * H_ * L_ * DK_) // 8388608
#define OUT0_ELEMS ((size_t)B_ * L_ * D_)

// ---------------- scratch (device globals) ------------------------------------
__device__ float g_sat_ln[TOK_ELEMS];
__device__ float g_ts_ln[TOK_ELEMS];
__device__ float g_q[PROJ_ELEMS];
__device__ float g_k[PROJ_ELEMS];
__device__ float g_ss[PROJ_ELEMS];
__device__ float g_cs[PROJ_ELEMS];
__device__ float g_st[PROJ_ELEMS];
__device__ float g_ct[PROJ_ELEMS];
__device__ float g_v[B_ * L_ * DK_];
__device__ float g_head[PROJ_ELEMS];
// transposed weights (K-major rows of length 512): (H, DK, D)
__device__ float g_WtQ[H_ * DK_ * D_];
__device__ float g_WtK[H_ * DK_ * D_];
__device__ float g_WtSat[H_ * DK_ * D_];
__device__ float g_WtTs[H_ * DK_ * D_];
__device__ float g_WtV[DK_ * D_];

// ---------------- PTX helpers (portable: compute_80+) --------------------------
__device__ __forceinline__ uint32_t smem_u32(const void* p) {
    uint32_t a;
    asm("{ .reg .u64 t; cvta.to.shared.u64 t, %1; cvt.u32.u64 %0, t; }" : "=r"(a) : "l"(p));
    return a;
}
#define CP_ASYNC16(dst, src) \
    asm volatile("cp.async.cg.shared.global [%0], [%1], 16;" :: "r"(dst), "l"(src) : "memory")
#define CP_COMMIT() asm volatile("cp.async.commit_group;" ::: "memory")
#define CP_WAIT0()  asm volatile("cp.async.wait_group 0;" ::: "memory")
#define CP_WAIT1()  asm volatile("cp.async.wait_group 1;" ::: "memory")

#define LDSM_X4(r0, r1, r2, r3, addr) \
    asm volatile("ldmatrix.sync.aligned.m8n8.x4.shared.b16 {%0,%1,%2,%3}, [%4];" \
        : "=r"(r0), "=r"(r1), "=r"(r2), "=r"(r3) : "r"(addr))

#define MMA_TF32(c, a0, a1, a2, a3, b0, b1) \
    asm volatile("mma.sync.aligned.m16n8k8.row.col.f32.tf32.tf32.f32 " \
        "{%0,%1,%2,%3},{%4,%5,%6,%7},{%8,%9},{%0,%1,%2,%3};" \
        : "+f"((c)[0]), "+f"((c)[1]), "+f"((c)[2]), "+f"((c)[3]) \
        : "r"(a0), "r"(a1), "r"(a2), "r"(a3), "r"(b0), "r"(b1))

// split fp32 x into big (tf32) + small (tf32 of residual)
__device__ __forceinline__ void tf32_split(uint32_t x, uint32_t& big, uint32_t& sml) {
    float xf = __uint_as_float(x);
    asm("cvt.rna.tf32.f32 %0, %1;" : "=r"(big) : "f"(xf));
    float r = xf - __uint_as_float(big);
    asm("cvt.rna.tf32.f32 %0, %1;" : "=r"(sml) : "f"(r));
}

// ---------------- LayerNorm ---------------------------------------------------
__global__ void ln_kernel(const float* __restrict__ sat, const float* __restrict__ ts,
                          const float* __restrict__ gs, const float* __restrict__ bs,
                          const float* __restrict__ gt, const float* __restrict__ bt)
{
    int rid = blockIdx.x;
    const float* src; float* dst; const float* g; const float* bb;
    if (rid < M_ROWS) {
        src = sat + (size_t)rid * D_; dst = g_sat_ln + (size_t)rid * D_; g = gs; bb = bs;
    } else {
        int r = rid - M_ROWS;
        src = ts + (size_t)r * D_;   dst = g_ts_ln + (size_t)r * D_;  g = gt; bb = bt;
    }
    int t = threadIdx.x;
    float4 x = ((const float4*)src)[t];
    float s  = x.x + x.y + x.z + x.w;
    float sq = x.x*x.x + x.y*x.y + x.z*x.z + x.w*x.w;
    #pragma unroll
    for (int o = 16; o; o >>= 1) {
        s  += __shfl_xor_sync(0xFFFFFFFFu, s,  o);
        sq += __shfl_xor_sync(0xFFFFFFFFu, sq, o);
    }
    __shared__ float ws[4], wq[4];
    if ((t & 31) == 0) { ws[t >> 5] = s; wq[t >> 5] = sq; }
    __syncthreads();
    s  = ws[0] + ws[1] + ws[2] + ws[3];
    sq = wq[0] + wq[1] + wq[2] + wq[3];
    float m   = s * (1.0f / D_);
    float var = sq * (1.0f / D_) - m * m;
    float inv = rsqrtf(var + 1e-5f);
    float4 g4 = ((const float4*)g)[t];
    float4 b4 = ((const float4*)bb)[t];
    float4 o;
    o.x = (x.x - m) * inv * g4.x + b4.x;
    o.y = (x.y - m) * inv * g4.y + b4.y;
    o.z = (x.z - m) * inv * g4.z + b4.z;
    o.w = (x.w - m) * inv * g4.w + b4.w;
    ((float4*)dst)[t] = o;
}

// ---------------- weight transpose: W (Hn,512,64) -> Wt (Hn,64,512) -----------
__global__ void transpose_w(const float* __restrict__ W, float* __restrict__ Wt)
{
    __shared__ float t[64][65];
    int h = blockIdx.x, k0 = blockIdx.y * 64;
    const float* Wp = W + (size_t)h * (D_ * DK_);
    float* Wo = Wt + (size_t)h * (DK_ * D_);
    #pragma unroll
    for (int i = 0; i < 16; i++) {
        int e = threadIdx.x + i * 256;
        int r = e >> 6, c = e & 63;
        t[r][c] = Wp[(size_t)(k0 + r) * 64 + c];
    }
    __syncthreads();
    #pragma unroll
    for (int i = 0; i < 16; i++) {
        int e = threadIdx.x + i * 256;
        int n = e >> 6, kk = e & 63;
        Wo[(size_t)n * 512 + k0 + kk] = t[kk][n];
    }
}

// ---------------- 3xTF32 mma.sync projection GEMM ------------------------------
// C = A (M x 512) @ Bt^T + bias, Bt rows are N (K-major length-512 rows).
// CTA tile 128x64, K stage 32, 2-stage cp.async pipeline; fp32-accurate via
// big/small tf32 decomposition (3 MMAs per logical MMA).
#define ASTRIDE 36                       // floats per smem row (144B)
#define ASZ (128 * ASTRIDE * 4)          // bytes
#define BSZ (64  * ASTRIDE * 4)
#define STG (ASZ + BSZ)
#define GEMM_SMEM (2 * STG)              // 55296 B

__global__ void __launch_bounds__(256) gemm_mma(const float* __restrict__ A,
                                                const float* __restrict__ Bt,
                                                const float* __restrict__ bias,
                                                float* __restrict__ C,
                                                int is_v)
{
    extern __shared__ __align__(16) char smraw[];
    uint32_t sb = smem_u32(smraw);
    int tid = threadIdx.x;
    int lane = tid & 31, wid = tid >> 5;
    int warp_m = wid >> 1, warp_n = wid & 1;
    int m0 = blockIdx.x * 128, by = blockIdx.y, n0 = by * 64;

    int t8 = lane & 7, sel = lane >> 3;
    uint32_t aOff = (uint32_t)(((warp_m * 32 + (sel & 1) * 8 + t8) * ASTRIDE + (sel >> 1) * 4) * 4);
    uint32_t bOff = (uint32_t)(((warp_n * 32 + (sel >> 1) * 8 + t8) * ASTRIDE + (sel & 1) * 4) * 4);

    float c[8][4];
    #pragma unroll
    for (int i = 0; i < 8; i++)
        #pragma unroll
        for (int j = 0; j < 4; j++) c[i][j] = 0.0f;

    auto load_stage = [&](int s, int k0) {
        uint32_t ab = sb + s * STG, bbs = ab + ASZ;
        #pragma unroll
        for (int i = 0; i < 4; i++) {
            int e = tid + i * 256, r = e >> 3, c4 = e & 7;
            CP_ASYNC16(ab + (uint32_t)((r * ASTRIDE + c4 * 4) * 4),
                       A + (size_t)(m0 + r) * 512 + k0 + c4 * 4);
        }
        #pragma unroll
        for (int i = 0; i < 2; i++) {
            int e = tid + i * 256, r = e >> 3, c4 = e & 7;
            CP_ASYNC16(bbs + (uint32_t)((r * ASTRIDE + c4 * 4) * 4),
                       Bt + (size_t)(n0 + r) * 512 + k0 + c4 * 4);
        }
    };

    auto compute = [&](int s) {
        uint32_t ab = sb + s * STG + aOff;
        uint32_t bb = sb + s * STG + ASZ + bOff;
        #pragma unroll
        for (int ks = 0; ks < 4; ks++) {
            uint32_t a[8], b[8];
            LDSM_X4(a[0], a[1], a[2], a[3], ab + ks * 32);
            LDSM_X4(a[4], a[5], a[6], a[7], ab + (uint32_t)(16 * ASTRIDE * 4) + ks * 32);
            LDSM_X4(b[0], b[1], b[2], b[3], bb + ks * 32);
            LDSM_X4(b[4], b[5], b[6], b[7], bb + (uint32_t)(16 * ASTRIDE * 4) + ks * 32);
            uint32_t aB[8], aS[8], bB[8], bS[8];
            #pragma unroll
            for (int i = 0; i < 8; i++) { tf32_split(a[i], aB[i], aS[i]); tf32_split(b[i], bB[i], bS[i]); }
            #pragma unroll
            for (int i = 0; i < 2; i++)
                #pragma unroll
                for (int j = 0; j < 4; j++) {
                    float* cc = c[i * 4 + j];
                    // small terms first (accumulate low-order parts before big)
                    MMA_TF32(cc, aS[i*4], aS[i*4+1], aS[i*4+2], aS[i*4+3], bB[j*2], bB[j*2+1]);
                    MMA_TF32(cc, aB[i*4], aB[i*4+1], aB[i*4+2], aB[i*4+3], bS[j*2], bS[j*2+1]);
                    MMA_TF32(cc, aB[i*4], aB[i*4+1], aB[i*4+2], aB[i*4+3], bB[j*2], bB[j*2+1]);
                }
        }
    };

    load_stage(0, 0);
    CP_COMMIT();
    for (int ck = 0; ck < 16; ck++) {
        if (ck < 15) {
            load_stage((ck + 1) & 1, (ck + 1) * 32);
            CP_COMMIT();
            CP_WAIT1();
        } else {
            CP_WAIT0();
        }
        __syncthreads();
        compute(ck & 1);
        __syncthreads();
    }

    // epilogue
    int r_lane = lane >> 2, c_lane = (lane & 3) * 2;
    #pragma unroll
    for (int i = 0; i < 2; i++) {
        #pragma unroll
        for (int j = 0; j < 4; j++) {
            float* cc = c[i * 4 + j];
            int nc = warp_n * 32 + j * 8 + c_lane;
            int mrow = m0 + warp_m * 32 + i * 16 + r_lane;
            float2 bb2;
            size_t base0, base1;
            if (is_v) {
                bb2 = *(const float2*)&bias[nc];
                base0 = (size_t)mrow * 64 + nc;
                base1 = (size_t)(mrow + 8) * 64 + nc;
            } else {
                bb2 = *(const float2*)&bias[by * 64 + nc];
                int b0r = mrow >> 10, l0r = mrow & 1023;
                int b1r = (mrow + 8) >> 10, l1r = (mrow + 8) & 1023;
                base0 = ((((size_t)(b0r * 8 + by)) << 10) + l0r) * 64 + nc;
                base1 = ((((size_t)(b1r * 8 + by)) << 10) + l1r) * 64 + nc;
            }
            float2 o0 = {cc[0] + bb2.x, cc[1] + bb2.y};
            float2 o1 = {cc[2] + bb2.x, cc[3] + bb2.y};
            *(float2*)&C[base0] = o0;
            *(float2*)&C[base1] = o1;
        }
    }
}

// ---------------- RoPE --------------------------------------------------------
__global__ void rope_kernel()
{
    const int Np = PROJ_ELEMS / 2;
    int idx = blockIdx.x * blockDim.x + threadIdx.x;
    float2 *xb; const float2 *cb, *sb;
    if (idx < Np) {
        xb = (float2*)g_q; cb = (const float2*)g_ct; sb = (const float2*)g_st;
    } else {
        idx -= Np;
        xb = (float2*)g_k; cb = (const float2*)g_cs; sb = (const float2*)g_ss;
    }
    float2 x = xb[idx];
    float2 c = cb[idx];
    float2 s = sb[idx];
    float2 o;
    o.x = x.x * c.x - x.y * s.x;
    o.y = x.y * c.y + x.x * s.y;
    xb[idx] = o;
}

// ---------------- attention ---------------------------------------------------
#define QT  32
#define KT  256
#define SCP 1025
#define KVP 68
#define ATTN_SMEM_FLOATS (QT * SCP + KT * KVP + QT * 64)

__global__ void __launch_bounds__(256) attn_kernel(float* __restrict__ attn_out)
{
    extern __shared__ __align__(16) float smf[];
    float* sc = smf;
    float* kv = smf + QT * SCP;
    float* qs = kv + KT * KVP;

    int tid = threadIdx.x;
    int q0 = blockIdx.x * QT;
    int h  = blockIdx.y;
    int b  = blockIdx.z;
    size_t bh = (size_t)(b * H_ + h);

    size_t qbase = ((bh << 10) + q0) * 64;
    #pragma unroll
    for (int i = 0; i < 2; i++) {
        int e = tid + i * 256;
        ((float4*)qs)[e] = *(const float4*)&g_q[qbase + (size_t)e * 4];
    }

    int ty = tid >> 5, tx = tid & 31;

    for (int kt = 0; kt < 4; kt++) {
        __syncthreads();
        size_t kbase = ((bh << 10) + kt * KT) * 64;
        #pragma unroll
        for (int i = 0; i < 16; i++) {
            int e = tid + i * 256;
            int r = e >> 4, c4 = e & 15;
            float4 a = *(const float4*)&g_k[kbase + (size_t)r * 64 + c4 * 4];
            *(float4*)&kv[r * KVP + c4 * 4] = a;
        }
        __syncthreads();
        float acc[4][8];
        #pragma unroll
        for (int i = 0; i < 4; i++)
            #pragma unroll
            for (int j = 0; j < 8; j++) acc[i][j] = 0.0f;
        #pragma unroll
        for (int d = 0; d < 64; d += 4) {
            float4 a[4];
            #pragma unroll
            for (int i = 0; i < 4; i++) a[i] = *(float4*)&qs[(ty * 4 + i) * 64 + d];
            #pragma unroll
            for (int j = 0; j < 8; j++) {
                float4 bk = *(float4*)&kv[(tx + 32 * j) * KVP + d];
                #pragma unroll
                for (int i = 0; i < 4; i++)
                    acc[i][j] += a[i].x * bk.x + a[i].y * bk.y + a[i].z * bk.z + a[i].w * bk.w;
            }
        }
        #pragma unroll
        for (int i = 0; i < 4; i++)
            #pragma unroll
            for (int j = 0; j < 8; j++)
                sc[(ty * 4 + i) * SCP + kt * KT + tx + 32 * j] = acc[i][j] * 0.125f;
    }
    __syncthreads();

    for (int rr = ty * 4; rr < ty * 4 + 4; rr++) {
        float vals[32];
        float mx = -1e30f;
        #pragma unroll
        for (int j = 0; j < 32; j++) {
            vals[j] = sc[rr * SCP + tx + 32 * j];
            mx = fmaxf(mx, vals[j]);
        }
        #pragma unroll
        for (int o = 16; o; o >>= 1) mx = fmaxf(mx, __shfl_xor_sync(0xFFFFFFFFu, mx, o));
        float s = 0.0f;
        #pragma unroll
        for (int j = 0; j < 32; j++) { vals[j] = __expf(vals[j] - mx); s += vals[j]; }
        #pragma unroll
        for (int o = 16; o; o >>= 1) s += __shfl_xor_sync(0xFFFFFFFFu, s, o);
        float inv = 1.0f / s;
        size_t obase = (((size_t)(b * L_ + q0 + rr) * H_ + h) << 10);
        #pragma unroll
        for (int j = 0; j < 32; j++) {
            float p = vals[j] * inv;
            sc[rr * SCP + tx + 32 * j] = p;
            attn_out[obase + tx + 32 * j] = p;
        }
    }
    __syncthreads();

    int r0 = (tid & 7) * 4;
    int c0 = (tid >> 3) * 2;
    float hacc[4][2];
    #pragma unroll
    for (int i = 0; i < 4; i++) { hacc[i][0] = 0.0f; hacc[i][1] = 0.0f; }
    for (int vt = 0; vt < 4; vt++) {
        __syncthreads();
        size_t vbase = ((size_t)b * L_ + vt * KT) * 64;
        #pragma unroll
        for (int i = 0; i < 16; i++) {
            int e = tid + i * 256;
            int r = e >> 4, c4 = e & 15;
            float4 a = *(const float4*)&g_v[vbase + (size_t)r * 64 + c4 * 4];
            *(float4*)&kv[r * KVP + c4 * 4] = a;
        }
        __syncthreads();
        #pragma unroll 4
        for (int kk = 0; kk < KT; kk++) {
            float v0 = kv[kk * KVP + c0];
            float v1 = kv[kk * KVP + c0 + 1];
            #pragma unroll
            for (int i = 0; i < 4; i++) {
                float p = sc[(r0 + i) * SCP + vt * KT + kk];
                hacc[i][0] += p * v0;
                hacc[i][1] += p * v1;
            }
        }
    }
    #pragma unroll
    for (int i = 0; i < 4; i++) {
        size_t hb = ((bh << 10) + q0 + r0 + i) * 64 + c0;
        g_head[hb]     = hacc[i][0];
        g_head[hb + 1] = hacc[i][1];
    }
}

// ---------------- final: out = mean_h(head) @ Wh ------------------------------
__global__ void __launch_bounds__(256) out_kernel(const float* __restrict__ Wh,
                                                  float* __restrict__ out)
{
    extern __shared__ __align__(16) float sm2[];
    __shared__ float hm[8][64];
    int tid = threadIdx.x;
    int m0 = blockIdx.x * 8;
    int bb = m0 >> 10;
    int l0 = m0 & 1023;

    #pragma unroll
    for (int i = 0; i < 32; i++) {
        int e = tid + i * 256;
        ((float4*)sm2)[e] = ((const float4*)Wh)[e];
    }
    #pragma unroll
    for (int i = 0; i < 2; i++) {
        int e = tid + i * 256;
        int r = e >> 6, kk = e & 63;
        float s = 0.0f;
        #pragma unroll
        for (int hh = 0; hh < 8; hh++)
            s += g_head[(((size_t)(bb * H_ + hh) << 10) + l0 + r) * 64 + kk];
        hm[r][kk] = s * 0.125f;
    }
    __syncthreads();

    int ty = tid >> 6;
    int tx = tid & 63;
    float acc[2][8];
    #pragma unroll
    for (int i = 0; i < 2; i++)
        #pragma unroll
        for (int j = 0; j < 8; j++) acc[i][j] = 0.0f;
    #pragma unroll 8
    for (int d = 0; d < 64; d++) {
        float a0 = hm[ty * 2][d];
        float a1 = hm[ty * 2 + 1][d];
        float4 w0 = *(float4*)&sm2[d * 512 + tx * 8];
        float4 w1 = *(float4*)&sm2[d * 512 + tx * 8 + 4];
        acc[0][0] += a0 * w0.x; acc[0][1] += a0 * w0.y; acc[0][2] += a0 * w0.z; acc[0][3] += a0 * w0.w;
        acc[0][4] += a0 * w1.x; acc[0][5] += a0 * w1.y; acc[0][6] += a0 * w1.z; acc[0][7] += a0 * w1.w;
        acc[1][0] += a1 * w0.x; acc[1][1] += a1 * w0.y; acc[1][2] += a1 * w0.z; acc[1][3] += a1 * w0.w;
        acc[1][4] += a1 * w1.x; acc[1][5] += a1 * w1.y; acc[1][6] += a1 * w1.z; acc[1][7] += a1 * w1.w;
    }
    #pragma unroll
    for (int i = 0; i < 2; i++) {
        int m = m0 + ty * 2 + i;
        float4 o0 = {acc[i][0], acc[i][1], acc[i][2], acc[i][3]};
        float4 o1 = {acc[i][4], acc[i][5], acc[i][6], acc[i][7]};
        *(float4*)&out[(size_t)m * 512 + tx * 8]     = o0;
        *(float4*)&out[(size_t)m * 512 + tx * 8 + 4] = o1;
    }
}

// ---------------- launch ------------------------------------------------------
extern "C" void kernel_launch(void* const* d_in, const int* in_sizes, int n_in,
                              void* d_out, int out_size)
{
    const float* sat     = (const float*)d_in[0];
    const float* satpos  = (const float*)d_in[1];
    const float* ts      = (const float*)d_in[2];
    const float* tspos   = (const float*)d_in[3];
    const float* lsg     = (const float*)d_in[4];
    const float* lsb     = (const float*)d_in[5];
    const float* ltg     = (const float*)d_in[6];
    const float* ltb     = (const float*)d_in[7];
    const float* Wv      = (const float*)d_in[8];
    const float* bv      = (const float*)d_in[9];
    const float* Wq      = (const float*)d_in[10];
    const float* bq      = (const float*)d_in[11];
    const float* Wk      = (const float*)d_in[12];
    const float* bk      = (const float*)d_in[13];
    const float* Wsat    = (const float*)d_in[14];
    const float* bsat    = (const float*)d_in[15];
    const float* Wts     = (const float*)d_in[16];
    const float* bts     = (const float*)d_in[17];
    const float* Wh      = (const float*)d_in[18];

    float* out      = (float*)d_out;
    float* attn_out = out + OUT0_ELEMS;

    float *p_satln, *p_tsln, *p_q, *p_k, *p_ss, *p_cs, *p_st, *p_ct, *p_v;
    float *p_WtQ, *p_WtK, *p_WtSat, *p_WtTs, *p_WtV;
    cudaGetSymbolAddress((void**)&p_satln, g_sat_ln);
    cudaGetSymbolAddress((void**)&p_tsln,  g_ts_ln);
    cudaGetSymbolAddress((void**)&p_q,     g_q);
    cudaGetSymbolAddress((void**)&p_k,     g_k);
    cudaGetSymbolAddress((void**)&p_ss,    g_ss);
    cudaGetSymbolAddress((void**)&p_cs,    g_cs);
    cudaGetSymbolAddress((void**)&p_st,    g_st);
    cudaGetSymbolAddress((void**)&p_ct,    g_ct);
    cudaGetSymbolAddress((void**)&p_v,     g_v);
    cudaGetSymbolAddress((void**)&p_WtQ,   g_WtQ);
    cudaGetSymbolAddress((void**)&p_WtK,   g_WtK);
    cudaGetSymbolAddress((void**)&p_WtSat, g_WtSat);
    cudaGetSymbolAddress((void**)&p_WtTs,  g_WtTs);
    cudaGetSymbolAddress((void**)&p_WtV,   g_WtV);

    const int attn_smem = ATTN_SMEM_FLOATS * 4;
    cudaFuncSetAttribute(attn_kernel, cudaFuncAttributeMaxDynamicSharedMemorySize, attn_smem);
    cudaFuncSetAttribute(out_kernel,  cudaFuncAttributeMaxDynamicSharedMemorySize, 64 * 512 * 4);
    cudaFuncSetAttribute(gemm_mma,    cudaFuncAttributeMaxDynamicSharedMemorySize, GEMM_SMEM);

    // 1. LayerNorms
    ln_kernel<<<2 * M_ROWS, 128>>>(sat, ts, lsg, lsb, ltg, ltb);

    // 2. transpose weights to K-major (full fp32)
    transpose_w<<<dim3(8, 8), 256>>>(Wq,   p_WtQ);
    transpose_w<<<dim3(8, 8), 256>>>(Wk,   p_WtK);
    transpose_w<<<dim3(8, 8), 256>>>(Wsat, p_WtSat);
    transpose_w<<<dim3(8, 8), 256>>>(Wts,  p_WtTs);
    transpose_w<<<dim3(1, 8), 256>>>(Wv,   p_WtV);

    // 3. 3xTF32 mma.sync projections
    dim3 gg(M_ROWS / 128, 8);
    gemm_mma<<<gg, 256, GEMM_SMEM>>>(p_tsln,             p_WtQ,   bq,   p_q,  0);
    gemm_mma<<<gg, 256, GEMM_SMEM>>>(p_satln,            p_WtK,   bk,   p_k,  0);
    gemm_mma<<<gg, 256, GEMM_SMEM>>>(satpos,             p_WtSat, bsat, p_ss, 0);
    gemm_mma<<<gg, 256, GEMM_SMEM>>>(satpos + TOK_ELEMS, p_WtSat, bsat, p_cs, 0);
    gemm_mma<<<gg, 256, GEMM_SMEM>>>(tspos,              p_WtTs,  bts,  p_st, 0);
    gemm_mma<<<gg, 256, GEMM_SMEM>>>(tspos + TOK_ELEMS,  p_WtTs,  bts,  p_ct, 0);
    gemm_mma<<<dim3(M_ROWS / 128, 1), 256, GEMM_SMEM>>>(p_satln, p_WtV, bv, p_v, 1);

    // 4. RoPE
    rope_kernel<<<PROJ_ELEMS / 256, 256>>>();

    // 5. attention
    dim3 ga(L_ / QT, H_, B_);
    attn_kernel<<<ga, 256, attn_smem>>>(attn_out);

    // 6. out = mean_h(head) @ Wh
    out_kernel<<<M_ROWS / 8, 256, 64 * 512 * 4>>>(Wh, out);
}